// round 11
// baseline (speedup 1.0000x reference)
#include <cuda_runtime.h>
#include <stdint.h>

// CoarseMatching, 2-pass, match = block-per-row-pair with smem-atomic
// candidates (bubble-minimized scan).
// conf [N, L, S] fp32, L = 4800, S = 4800.
// Outputs (concatenated fp32): mconf [N*L], mask_v [N*L], all_j_ids [N*L].
//
// Pass 1 (colmax): full read, per-column max via atomicMax on float bits.
// Pass 2 (match): colmax staged in SMEM (border/THR-poisoned). Valid rows
//   processed two at a time; per element 1 fmax + 1 bits==colmax compare;
//   hits (rare) go to per-row 64-bit smem atomicMax key (value, then
//   smallest j). Row reduction = single-value shuffle max. Outputs written
//   only for hits (rest pre-zeroed by memset).

#define THR  0.2f
#define BRM  2
#define H0   60
#define W0   80
#define H1   60
#define W1   80
#define LSZ  (H0 * W0)   // 4800
#define SSZ  (H1 * W1)   // 4800
#define MAXN 16
#define NF4  (SSZ / 4)   // 1200
#define RPB  28
#define VL0  (BRM * W0)              // 160
#define NVR  (LSZ - 2 * BRM * W0)    // 4480
#define GROUPS (NVR / RPB)           // 160
#define SLOTS 5

typedef unsigned long long ull;

__device__ unsigned int g_colmax[MAXN * SSZ];

__global__ __launch_bounds__(256) void colmax_kernel(const float* __restrict__ conf) {
    const int n  = blockIdx.z;
    const int i4 = blockIdx.x * blockDim.x + threadIdx.x;
    if (i4 >= NF4) return;
    const int l0 = blockIdx.y * 100;

    const float4* p = reinterpret_cast<const float4*>(
        conf + ((size_t)n * LSZ + (size_t)l0) * SSZ) + i4;

    float4 m = make_float4(0.f, 0.f, 0.f, 0.f);
    #pragma unroll 5
    for (int t = 0; t < 100; ++t) {
        const float4 v = *p;
        m.x = fmaxf(m.x, v.x);
        m.y = fmaxf(m.y, v.y);
        m.z = fmaxf(m.z, v.z);
        m.w = fmaxf(m.w, v.w);
        p += NF4;
    }
    unsigned int* cm = g_colmax + (size_t)n * SSZ + (size_t)i4 * 4;
    atomicMax(cm + 0, __float_as_uint(m.x));
    atomicMax(cm + 1, __float_as_uint(m.y));
    atomicMax(cm + 2, __float_as_uint(m.z));
    atomicMax(cm + 3, __float_as_uint(m.w));
}

// scan-update for one float4 of one row: rowmax chains + rare candidate atomic
__device__ __forceinline__ void scan4(const float4 v, const uint4 c, const int s0,
                                      float& m0, float& m1, float& m2, float& m3,
                                      ull* cand) {
    m0 = fmaxf(m0, v.x);
    m1 = fmaxf(m1, v.y);
    m2 = fmaxf(m2, v.z);
    m3 = fmaxf(m3, v.w);
    const bool c0 = (__float_as_uint(v.x) == c.x);
    const bool c1 = (__float_as_uint(v.y) == c.y);
    const bool c2 = (__float_as_uint(v.z) == c.z);
    const bool c3 = (__float_as_uint(v.w) == c.w);
    if (c0 | c1 | c2 | c3) {                       // ~1 per 1200 float4s
        if (c0) atomicMax(cand, ((ull)__float_as_uint(v.x) << 32) | (ull)(0xFFFFFFFFu - (unsigned)(s0 + 0)));
        if (c1) atomicMax(cand, ((ull)__float_as_uint(v.y) << 32) | (ull)(0xFFFFFFFFu - (unsigned)(s0 + 1)));
        if (c2) atomicMax(cand, ((ull)__float_as_uint(v.z) << 32) | (ull)(0xFFFFFFFFu - (unsigned)(s0 + 2)));
        if (c3) atomicMax(cand, ((ull)__float_as_uint(v.w) << 32) | (ull)(0xFFFFFFFFu - (unsigned)(s0 + 3)));
    }
}

__device__ __forceinline__ float warp_max(float m) {
    #pragma unroll
    for (int off = 16; off; off >>= 1)
        m = fmaxf(m, __shfl_down_sync(0xFFFFFFFFu, m, off));
    return m;
}

__global__ __launch_bounds__(256) void match_kernel(const float* __restrict__ conf,
                                                    float* __restrict__ out, int N) {
    __shared__ unsigned s_cm[SSZ];                 // 19.2 KB poisoned colmax
    __shared__ ull      s_cand[RPB];
    __shared__ float    s_m[RPB][8];
    __shared__ unsigned char s_vr[RPB];
    __shared__ int      s_nv;

    const int tid   = threadIdx.x;
    const int n     = blockIdx.x / GROUPS;
    const int lbase = VL0 + (blockIdx.x % GROUPS) * RPB;
    const int NL    = N * LSZ;
    const int w     = tid >> 5;

    // Stage colmax into SMEM; poison border-invalid and <=THR columns with
    // 0xFFFFFFFF (unreachable by any conf bit pattern < 1.0f).
    #pragma unroll
    for (int k = 0; k < SLOTS; ++k) {
        const int i = tid + k * 256;
        if (k < SLOTS - 1 || i < NF4) {
            uint4 c = *reinterpret_cast<const uint4*>(
                g_colmax + (size_t)n * SSZ + (size_t)i * 4);
            const int s0 = i * 4;
            const int sr = s0 / W1, sc = s0 % W1;  // 4 | W1: same sr for all 4
            const bool rok = (sr >= BRM) && (sr < H1 - BRM);
            if (!(rok && sc + 0 >= BRM && sc + 0 < W1 - BRM) || __uint_as_float(c.x) <= THR) c.x = 0xFFFFFFFFu;
            if (!(rok && sc + 1 >= BRM && sc + 1 < W1 - BRM) || __uint_as_float(c.y) <= THR) c.y = 0xFFFFFFFFu;
            if (!(rok && sc + 2 >= BRM && sc + 2 < W1 - BRM) || __uint_as_float(c.z) <= THR) c.z = 0xFFFFFFFFu;
            if (!(rok && sc + 3 >= BRM && sc + 3 < W1 - BRM) || __uint_as_float(c.w) <= THR) c.w = 0xFFFFFFFFu;
            *reinterpret_cast<uint4*>(&s_cm[s0]) = c;
        }
    }
    if (tid == 0) {                                // valid-row list (uniform)
        int nv = 0;
        #pragma unroll
        for (int r = 0; r < RPB; ++r) {
            const int lc = (lbase + r) % W0;
            if (lc >= BRM && lc < W0 - BRM) s_vr[nv++] = (unsigned char)r;
        }
        s_nv = nv;
    }
    if (tid < RPB) s_cand[tid] = 0ull;
    __syncthreads();

    const int nv = s_nv;
    const uint4* cm4 = reinterpret_cast<const uint4*>(s_cm);
    const float4* base = reinterpret_cast<const float4*>(
        conf + ((size_t)n * LSZ + (size_t)lbase) * SSZ);

    #pragma unroll 1
    for (int p = 0; p < nv; p += 2) {
        const int rA = s_vr[p];
        if (p + 1 < nv) {
            const int rB = s_vr[p + 1];
            const float4* rowA = base + (size_t)rA * NF4;
            const float4* rowB = base + (size_t)rB * NF4;
            float a0 = 0.f, a1 = 0.f, a2 = 0.f, a3 = 0.f;
            float b0 = 0.f, b1 = 0.f, b2 = 0.f, b3 = 0.f;
            #pragma unroll
            for (int k = 0; k < SLOTS; ++k) {
                const int i = tid + k * 256;
                if (k < SLOTS - 1 || i < NF4) {
                    const float4 va = rowA[i];
                    const float4 vb = rowB[i];
                    const uint4  c  = cm4[i];
                    scan4(va, c, i * 4, a0, a1, a2, a3, &s_cand[rA]);
                    scan4(vb, c, i * 4, b0, b1, b2, b3, &s_cand[rB]);
                }
            }
            const float mA = warp_max(fmaxf(fmaxf(a0, a1), fmaxf(a2, a3)));
            const float mB = warp_max(fmaxf(fmaxf(b0, b1), fmaxf(b2, b3)));
            if ((tid & 31) == 0) { s_m[rA][w] = mA; s_m[rB][w] = mB; }
        } else {
            const float4* rowA = base + (size_t)rA * NF4;
            float a0 = 0.f, a1 = 0.f, a2 = 0.f, a3 = 0.f;
            #pragma unroll
            for (int k = 0; k < SLOTS; ++k) {
                const int i = tid + k * 256;
                if (k < SLOTS - 1 || i < NF4) {
                    scan4(rowA[i], cm4[i], i * 4, a0, a1, a2, a3, &s_cand[rA]);
                }
            }
            const float mA = warp_max(fmaxf(fmaxf(a0, a1), fmaxf(a2, a3)));
            if ((tid & 31) == 0) s_m[rA][w] = mA;
        }
    }

    __syncthreads();

    if (tid < nv) {
        const int r = s_vr[tid];
        const int l = lbase + r;
        float m = s_m[r][0];
        #pragma unroll
        for (int w2 = 1; w2 < 8; ++w2) m = fmaxf(m, s_m[r][w2]);
        const ull cand = s_cand[r];
        if (cand != 0ull && (unsigned)(cand >> 32) == __float_as_uint(m)) {
            const int o = n * LSZ + l;
            out[o]          = m;
            out[NL + o]     = 1.f;
            out[2 * NL + o] = (float)(0xFFFFFFFFu - (unsigned)(cand & 0xFFFFFFFFull));
        }
    }
}

extern "C" void kernel_launch(void* const* d_in, const int* in_sizes, int n_in,
                              void* d_out, int out_size) {
    const float* conf = (const float*)d_in[0];
    const long long total = (long long)in_sizes[0];
    int N = (int)(total / ((long long)LSZ * (long long)SSZ));
    if (N < 1) N = 1;
    if (N > MAXN) N = MAXN;

    void* cm_ptr = nullptr;
    cudaGetSymbolAddress(&cm_ptr, g_colmax);
    cudaMemsetAsync(cm_ptr, 0, (size_t)N * SSZ * sizeof(unsigned int));
    cudaMemsetAsync(d_out, 0, (size_t)out_size * sizeof(float));

    dim3 g1((NF4 + 255) / 256, LSZ / 100, N);      // (5, 48, N)
    colmax_kernel<<<g1, 256>>>(conf);

    match_kernel<<<N * GROUPS, 256>>>(conf, (float*)d_out, N);   // 640 blocks
}